// round 14
// baseline (speedup 1.0000x reference)
#include <cuda_runtime.h>
#include <cstdint>

// Problem constants
static constexpr int SEQ = 2048;
static constexpr int DMODEL = 768;
static constexpr int NH = 12;
static constexpr int HD = 64;
static constexpr int WN = 129;
static constexpr int QT = 64;
static constexpr int KT = 192;
static constexpr int PK = 65;
static constexpr int PS = 132;

// Scratch (device globals: no cudaMalloc allowed)
__device__ float g_q[SEQ * DMODEL];
__device__ float g_k[SEQ * DMODEL];
__device__ float g_v[SEQ * DMODEL];
__device__ float g_ctx[SEQ * DMODEL];

// ---------------------------------------------------------------------------
// Helpers (sm_80+ PTX only — harness targets sm_103 base, NO tcgen05/'a' feats)
// ---------------------------------------------------------------------------
__device__ __forceinline__ void cp_async16(void* dst, const void* src) {
    uint32_t d;
    asm("{ .reg .u64 t; cvta.to.shared.u64 t, %1; cvt.u32.u64 %0, t; }"
        : "=r"(d) : "l"(dst));
    asm volatile("cp.async.cg.shared.global [%0], [%1], 16;"
                 :: "r"(d), "l"(src) : "memory");
}
__device__ __forceinline__ void cp_async_wait_all() {
    asm volatile("cp.async.commit_group;" ::: "memory");
    asm volatile("cp.async.wait_group 0;" ::: "memory");
}
__device__ __forceinline__ uint32_t cvt_tf32(float x) {
    uint32_t r;
    asm("cvt.rna.tf32.f32 %0, %1;" : "=r"(r) : "f"(x));
    return r;
}
__device__ __forceinline__ void mma_tf32(
    float& c0, float& c1, float& c2, float& c3,
    uint32_t a0, uint32_t a1, uint32_t a2, uint32_t a3,
    uint32_t b0, uint32_t b1)
{
    asm volatile(
        "mma.sync.aligned.m16n8k8.row.col.f32.tf32.tf32.f32 "
        "{%0,%1,%2,%3}, {%4,%5,%6,%7}, {%8,%9}, {%0,%1,%2,%3};"
        : "+f"(c0), "+f"(c1), "+f"(c2), "+f"(c3)
        : "r"(a0), "r"(a1), "r"(a2), "r"(a3), "r"(b0), "r"(b1));
}

// ---------------------------------------------------------------------------
// TF32 mma.sync GEMM: C = A @ W + bias.
// A: MxK row-major fp32.  W: KxN row-major fp32.
// CTA tile 128x128, k-chunk 32, 256 threads = 2(m) x 4(n) warps,
// warp tile 64x32 = 4x4 frags of m16n8k8. Double-buffered smem, pitch 36
// (conflict-free fragment LDS: bank = (4*row + col) mod 32, all distinct).
// blockIdx.z selects among 3 (A,W,bias,C) tuples (fused QKV).
// ---------------------------------------------------------------------------
static constexpr int GM = 128, GN = 128, GKC = 32;
static constexpr int PA = 36;                    // smem pitch (floats)
static constexpr int ASZF = 128 * PA;            // floats per A buffer (4608)
static constexpr int BSZF = 128 * PA;            // floats per B buffer
static constexpr int GEMM_SMEM = (2 * ASZF + 2 * BSZF) * 4;   // 73728 B

__global__ __launch_bounds__(256) void tf32_gemm_kernel(
    const float* __restrict__ A0, const float* __restrict__ B0,
    const float* __restrict__ bias0, float* __restrict__ C0,
    const float* __restrict__ A1, const float* __restrict__ B1,
    const float* __restrict__ bias1, float* __restrict__ C1,
    const float* __restrict__ A2, const float* __restrict__ B2,
    const float* __restrict__ bias2, float* __restrict__ C2,
    int M, int N, int K)
{
    extern __shared__ float sm[];
    float* sA[2] = { sm, sm + ASZF };
    float* sB[2] = { sm + 2 * ASZF, sm + 2 * ASZF + BSZF };

    const int z = blockIdx.z;
    const float* Ag   = (z == 0) ? A0    : (z == 1) ? A1    : A2;
    const float* Wg   = (z == 0) ? B0    : (z == 1) ? B1    : B2;
    const float* bias = (z == 0) ? bias0 : (z == 1) ? bias1 : bias2;
    float*       Cg   = (z == 0) ? C0    : (z == 1) ? C1    : C2;

    const int tid  = threadIdx.x;
    const int wid  = tid >> 5;
    const int lane = tid & 31;
    const int warp_m = wid >> 2;          // 0..1
    const int warp_n = wid & 3;           // 0..3
    const int grp  = lane >> 2;           // 0..7
    const int t4   = lane & 3;            // 0..3

    const int bm = blockIdx.y * GM;
    const int bn = blockIdx.x * GN;
    const int NCH = K / GKC;              // 24

    // A loader: 4 x cp.async 16B per thread into pitch-36 rows
    auto loadA = [&](int buf, int kc) {
        float* dst = sA[buf];
        #pragma unroll
        for (int i = 0; i < 4; i++) {
            const int idx = tid + 256 * i;          // 0..1023
            const int r = idx >> 3, c16 = idx & 7;  // row, 16B chunk
            cp_async16(dst + r * PA + c16 * 4,
                       Ag + (size_t)(bm + r) * K + kc * GKC + c16 * 4);
        }
    };
    // B loader: transpose W[k][n] -> sB[n][k], cvt.rna at store.
    // Lanes span n (coalesced LDG); each thread 4 k-groups of 4.
    auto loadB = [&](int buf, int kc) {
        float* dst = sB[buf];
        const int nn = tid & 127;
        const int h  = tid >> 7;                    // 0..1
        float4 vb[4];
        #pragma unroll
        for (int j = 0; j < 4; j++) {
            const int r4 = h + 2 * j;               // 0..7
            const float* src = Wg + (size_t)(kc * GKC + r4 * 4) * N + bn + nn;
            vb[j].x = src[0];
            vb[j].y = src[(size_t)N];
            vb[j].z = src[(size_t)2 * N];
            vb[j].w = src[(size_t)3 * N];
        }
        #pragma unroll
        for (int j = 0; j < 4; j++) {
            const int r4 = h + 2 * j;
            float4 o;
            o.x = __uint_as_float(cvt_tf32(vb[j].x));
            o.y = __uint_as_float(cvt_tf32(vb[j].y));
            o.z = __uint_as_float(cvt_tf32(vb[j].z));
            o.w = __uint_as_float(cvt_tf32(vb[j].w));
            *(float4*)(dst + nn * PA + r4 * 4) = o;  // conflict-free STS.128
        }
    };

    float acc[4][4][4];
    #pragma unroll
    for (int i = 0; i < 4; i++)
        #pragma unroll
        for (int j = 0; j < 4; j++)
            #pragma unroll
            for (int c = 0; c < 4; c++) acc[i][j][c] = 0.f;

    loadA(0, 0);
    loadB(0, 0);
    cp_async_wait_all();
    __syncthreads();

    for (int i = 0; i < NCH; i++) {
        const int b = i & 1;
        if (i + 1 < NCH) {            // prefetch next chunk into other buffer
            loadA(b ^ 1, i + 1);
            loadB(b ^ 1, i + 1);
        }
        const float* As = sA[b];
        const float* Bs = sB[b];
        #pragma unroll
        for (int k8 = 0; k8 < 4; k8++) {
            uint32_t a[4][4];
            #pragma unroll
            for (int mf = 0; mf < 4; mf++) {
                const float* ap =
                    As + (warp_m * 64 + mf * 16 + grp) * PA + k8 * 8 + t4;
                a[mf][0] = cvt_tf32(ap[0]);
                a[mf][2] = cvt_tf32(ap[4]);
                a[mf][1] = cvt_tf32(ap[8 * PA]);
                a[mf][3] = cvt_tf32(ap[8 * PA + 4]);
            }
            #pragma unroll
            for (int nf = 0; nf < 4; nf++) {
                const float* bp =
                    Bs + (warp_n * 32 + nf * 8 + grp) * PA + k8 * 8 + t4;
                const uint32_t b0 = __float_as_uint(bp[0]);
                const uint32_t b1 = __float_as_uint(bp[4]);
                #pragma unroll
                for (int mf = 0; mf < 4; mf++)
                    mma_tf32(acc[mf][nf][0], acc[mf][nf][1],
                             acc[mf][nf][2], acc[mf][nf][3],
                             a[mf][0], a[mf][1], a[mf][2], a[mf][3], b0, b1);
            }
        }
        if (i + 1 < NCH) cp_async_wait_all();
        __syncthreads();
    }

    // Epilogue: fragment -> gmem with bias (float2 stores, col even)
    #pragma unroll
    for (int mf = 0; mf < 4; mf++) {
        const int row = bm + warp_m * 64 + mf * 16 + grp;
        #pragma unroll
        for (int nf = 0; nf < 4; nf++) {
            const int col = bn + warp_n * 32 + nf * 8 + t4 * 2;
            const float bx = __ldg(&bias[col]);
            const float by = __ldg(&bias[col + 1]);
            float2 lo, hi;
            lo.x = acc[mf][nf][0] + bx;
            lo.y = acc[mf][nf][1] + by;
            hi.x = acc[mf][nf][2] + bx;
            hi.y = acc[mf][nf][3] + by;
            *(float2*)&Cg[(size_t)row * N + col] = lo;
            *(float2*)&Cg[(size_t)(row + 8) * N + col] = hi;
        }
    }
}

// ---------------------------------------------------------------------------
// Sliding-window attention (unchanged from passing R10 baseline).
// ---------------------------------------------------------------------------
__global__ __launch_bounds__(256) void swa_kernel()
{
    extern __shared__ float smattn[];
    float* sQ = smattn;
    float* sK = sQ + QT * PK;
    float* sV = sK + KT * PK;
    float* sS = sV + KT * PK;

    const int tid   = threadIdx.x;
    const int qbase = blockIdx.x * QT;
    const int h     = blockIdx.y;

    for (int idx = tid; idx < QT * HD; idx += 256) {
        const int r = idx >> 6, d = idx & 63;
        sQ[r * PK + d] = g_q[(size_t)(qbase + r) * DMODEL + h * HD + d];
    }
    for (int idx = tid; idx < KT * HD; idx += 256) {
        const int r = idx >> 6, d = idx & 63;
        const int pos = qbase - 64 + r;
        const bool ok = (pos >= 0) && (pos < SEQ);
        const size_t off = ok ? ((size_t)pos * DMODEL + h * HD + d) : 0;
        sK[r * PK + d] = ok ? g_k[off] : 0.f;
        sV[r * PK + d] = ok ? g_v[off] : 0.f;
    }
    __syncthreads();

    const int warp = tid >> 5;
    const int lane = tid & 31;

    for (int r8 = 0; r8 < 8; r8++) {
        const int qi = warp * 8 + r8;
        const float* qrow = sQ + qi * PK;
        const float* k0 = sK + min(qi + lane +   0, KT - 1) * PK;
        const float* k1 = sK + min(qi + lane +  32, KT - 1) * PK;
        const float* k2 = sK + min(qi + lane +  64, KT - 1) * PK;
        const float* k3 = sK + min(qi + lane +  96, KT - 1) * PK;
        const float* k4 = sK + min(qi + lane + 128, KT - 1) * PK;
        float a0 = 0.f, a1 = 0.f, a2 = 0.f, a3 = 0.f, a4 = 0.f;
        #pragma unroll 8
        for (int d = 0; d < HD; d++) {
            const float qv = qrow[d];
            a0 += qv * k0[d];
            a1 += qv * k1[d];
            a2 += qv * k2[d];
            a3 += qv * k3[d];
            a4 += qv * k4[d];
        }
        float accs[5] = {a0, a1, a2, a3, a4};
        #pragma unroll
        for (int c = 0; c < 5; c++) {
            const int w = lane + 32 * c;
            if (w < PS) {
                const int pos = qbase + qi - 64 + w;
                const float s = (w < WN && pos >= 0 && pos < SEQ)
                                    ? accs[c] * 0.125f : -1e30f;
                sS[qi * PS + w] = s;
            }
        }
    }
    __syncwarp();

    for (int r8 = 0; r8 < 8; r8++) {
        const int qi = warp * 8 + r8;
        float v[5];
        float m = -1e30f;
        #pragma unroll
        for (int c = 0; c < 5; c++) {
            const int w = lane + 32 * c;
            v[c] = (w < PS) ? sS[qi * PS + w] : -1e30f;
            m = fmaxf(m, v[c]);
        }
        #pragma unroll
        for (int o = 16; o > 0; o >>= 1)
            m = fmaxf(m, __shfl_xor_sync(0xffffffffu, m, o));
        float sum = 0.f;
        #pragma unroll
        for (int c = 0; c < 5; c++) { v[c] = __expf(v[c] - m); sum += v[c]; }
        #pragma unroll
        for (int o = 16; o > 0; o >>= 1)
            sum += __shfl_xor_sync(0xffffffffu, sum, o);
        const float inv = __frcp_rn(sum);
        #pragma unroll
        for (int c = 0; c < 5; c++) {
            const int w = lane + 32 * c;
            if (w < PS) sS[qi * PS + w] = v[c] * inv;
        }
    }
    __syncwarp();

    for (int r8 = 0; r8 < 8; r8++) {
        const int qi = warp * 8 + r8;
        const float* prow  = sS + qi * PS;
        const float* vbase = sV + qi * PK;
        float c0 = 0.f, c1 = 0.f;
        #pragma unroll 3
        for (int w = 0; w < WN; w++) {
            const float p = prow[w];
            c0 += p * vbase[w * PK + lane];
            c1 += p * vbase[w * PK + lane + 32];
        }
        const size_t row = (size_t)(qbase + qi) * DMODEL + h * HD;
        g_ctx[row + lane]      = c0;
        g_ctx[row + lane + 32] = c1;
    }
}

// ---------------------------------------------------------------------------
extern "C" void kernel_launch(void* const* d_in, const int* in_sizes, int n_in,
                              void* d_out, int out_size)
{
    (void)in_sizes; (void)n_in; (void)out_size;
    const float* query = (const float*)d_in[0];
    const float* key   = (const float*)d_in[1];
    const float* value = (const float*)d_in[2];
    const float* Wq = (const float*)d_in[3];
    const float* bq = (const float*)d_in[4];
    const float* Wk = (const float*)d_in[5];
    const float* bk = (const float*)d_in[6];
    const float* Wv = (const float*)d_in[7];
    const float* bv = (const float*)d_in[8];
    const float* Wo = (const float*)d_in[9];
    const float* bo = (const float*)d_in[10];
    float* out = (float*)d_out;

    float *qp, *kp, *vp, *cp;
    cudaGetSymbolAddress((void**)&qp, g_q);
    cudaGetSymbolAddress((void**)&kp, g_k);
    cudaGetSymbolAddress((void**)&vp, g_v);
    cudaGetSymbolAddress((void**)&cp, g_ctx);

    const size_t smem_attn =
        (size_t)(QT * PK + 2 * KT * PK + QT * PS) * sizeof(float);
    cudaFuncSetAttribute(swa_kernel,
                         cudaFuncAttributeMaxDynamicSharedMemorySize,
                         (int)smem_attn);
    cudaFuncSetAttribute(tf32_gemm_kernel,
                         cudaFuncAttributeMaxDynamicSharedMemorySize,
                         GEMM_SMEM);

    // Fused QKV projection (tf32 mma.sync tensor cores)
    dim3 gproj(DMODEL / GN, SEQ / GM, 3);   // (6, 16, 3)
    tf32_gemm_kernel<<<gproj, 256, GEMM_SMEM>>>(
        query, Wq, bq, qp,
        key,   Wk, bk, kp,
        value, Wv, bv, vp,
        SEQ, DMODEL, DMODEL);

    // Sliding-window attention
    swa_kernel<<<dim3(SEQ / QT, NH), 256, smem_attn>>>();

    // Output projection -> d_out
    dim3 gout(DMODEL / GN, SEQ / GM, 1);    // (6, 16)
    tf32_gemm_kernel<<<gout, 256, GEMM_SMEM>>>(
        cp, Wo, bo, out,
        cp, Wo, bo, out,
        cp, Wo, bo, out,
        SEQ, DMODEL, DMODEL);
}

// round 15
// speedup vs baseline: 1.6127x; 1.6127x over previous
#include <cuda_runtime.h>
#include <cstdint>

// Problem constants
static constexpr int SEQ = 2048;
static constexpr int DMODEL = 768;
static constexpr int NH = 12;
static constexpr int HD = 64;
static constexpr int WN = 129;
static constexpr int QT = 64;

// Scratch (device globals: no cudaMalloc allowed)
__device__ float g_q[SEQ * DMODEL];
__device__ float g_k[SEQ * DMODEL];
__device__ float g_v[SEQ * DMODEL];
__device__ float g_ctx[SEQ * DMODEL];

// ---------------------------------------------------------------------------
// Helpers (sm_80+ PTX only — harness targets sm_103 base, NO tcgen05/'a' feats)
// ---------------------------------------------------------------------------
__device__ __forceinline__ void cp_async16(void* dst, const void* src) {
    uint32_t d;
    asm("{ .reg .u64 t; cvta.to.shared.u64 t, %1; cvt.u32.u64 %0, t; }"
        : "=r"(d) : "l"(dst));
    asm volatile("cp.async.cg.shared.global [%0], [%1], 16;"
                 :: "r"(d), "l"(src) : "memory");
}
__device__ __forceinline__ void cp_async_wait_all() {
    asm volatile("cp.async.commit_group;" ::: "memory");
    asm volatile("cp.async.wait_group 0;" ::: "memory");
}
__device__ __forceinline__ uint32_t cvt_tf32(float x) {
    uint32_t r;
    asm("cvt.rna.tf32.f32 %0, %1;" : "=r"(r) : "f"(x));
    return r;
}
__device__ __forceinline__ float cvt_tf32f(float x) {
    return __uint_as_float(cvt_tf32(x));
}
__device__ __forceinline__ void mma_tf32(
    float& c0, float& c1, float& c2, float& c3,
    uint32_t a0, uint32_t a1, uint32_t a2, uint32_t a3,
    uint32_t b0, uint32_t b1)
{
    asm volatile(
        "mma.sync.aligned.m16n8k8.row.col.f32.tf32.tf32.f32 "
        "{%0,%1,%2,%3}, {%4,%5,%6,%7}, {%8,%9}, {%0,%1,%2,%3};"
        : "+f"(c0), "+f"(c1), "+f"(c2), "+f"(c3)
        : "r"(a0), "r"(a1), "r"(a2), "r"(a3), "r"(b0), "r"(b1));
}

// ---------------------------------------------------------------------------
// TF32 mma.sync GEMM: C = A @ W + bias. (layout verified in R14)
// CTA tile 128x128, k-chunk 32, 256 threads, warp tile 64x32.
// __launch_bounds__(256,2): cap regs at 128 -> 2 CTA/SM (occupancy fix).
// ---------------------------------------------------------------------------
static constexpr int GM = 128, GN = 128, GKC = 32;
static constexpr int PA = 36;
static constexpr int ASZF = 128 * PA;
static constexpr int BSZF = 128 * PA;
static constexpr int GEMM_SMEM = (2 * ASZF + 2 * BSZF) * 4;   // 73728 B

__global__ __launch_bounds__(256, 2) void tf32_gemm_kernel(
    const float* __restrict__ A0, const float* __restrict__ B0,
    const float* __restrict__ bias0, float* __restrict__ C0,
    const float* __restrict__ A1, const float* __restrict__ B1,
    const float* __restrict__ bias1, float* __restrict__ C1,
    const float* __restrict__ A2, const float* __restrict__ B2,
    const float* __restrict__ bias2, float* __restrict__ C2,
    int M, int N, int K)
{
    extern __shared__ float smg[];
    float* sA[2] = { smg, smg + ASZF };
    float* sB[2] = { smg + 2 * ASZF, smg + 2 * ASZF + BSZF };

    const int z = blockIdx.z;
    const float* Ag   = (z == 0) ? A0    : (z == 1) ? A1    : A2;
    const float* Wg   = (z == 0) ? B0    : (z == 1) ? B1    : B2;
    const float* bias = (z == 0) ? bias0 : (z == 1) ? bias1 : bias2;
    float*       Cg   = (z == 0) ? C0    : (z == 1) ? C1    : C2;

    const int tid  = threadIdx.x;
    const int wid  = tid >> 5;
    const int lane = tid & 31;
    const int warp_m = wid >> 2;
    const int warp_n = wid & 3;
    const int grp  = lane >> 2;
    const int t4   = lane & 3;

    const int bm = blockIdx.y * GM;
    const int bn = blockIdx.x * GN;
    const int NCH = K / GKC;

    auto loadA = [&](int buf, int kc) {
        float* dst = sA[buf];
        #pragma unroll
        for (int i = 0; i < 4; i++) {
            const int idx = tid + 256 * i;
            const int r = idx >> 3, c16 = idx & 7;
            cp_async16(dst + r * PA + c16 * 4,
                       Ag + (size_t)(bm + r) * K + kc * GKC + c16 * 4);
        }
    };
    auto loadB = [&](int buf, int kc) {
        float* dst = sB[buf];
        const int nn = tid & 127;
        const int hh = tid >> 7;
        float4 vb[4];
        #pragma unroll
        for (int j = 0; j < 4; j++) {
            const int r4 = hh + 2 * j;
            const float* src = Wg + (size_t)(kc * GKC + r4 * 4) * N + bn + nn;
            vb[j].x = src[0];
            vb[j].y = src[(size_t)N];
            vb[j].z = src[(size_t)2 * N];
            vb[j].w = src[(size_t)3 * N];
        }
        #pragma unroll
        for (int j = 0; j < 4; j++) {
            const int r4 = hh + 2 * j;
            float4 o;
            o.x = cvt_tf32f(vb[j].x);
            o.y = cvt_tf32f(vb[j].y);
            o.z = cvt_tf32f(vb[j].z);
            o.w = cvt_tf32f(vb[j].w);
            *(float4*)(dst + nn * PA + r4 * 4) = o;
        }
    };

    float acc[4][4][4];
    #pragma unroll
    for (int i = 0; i < 4; i++)
        #pragma unroll
        for (int j = 0; j < 4; j++)
            #pragma unroll
            for (int c = 0; c < 4; c++) acc[i][j][c] = 0.f;

    loadA(0, 0);
    loadB(0, 0);
    cp_async_wait_all();
    __syncthreads();

    for (int i = 0; i < NCH; i++) {
        const int b = i & 1;
        if (i + 1 < NCH) {
            loadA(b ^ 1, i + 1);
            loadB(b ^ 1, i + 1);
        }
        const float* As = sA[b];
        const float* Bs = sB[b];
        #pragma unroll
        for (int k8 = 0; k8 < 4; k8++) {
            uint32_t a[4][4];
            #pragma unroll
            for (int mf = 0; mf < 4; mf++) {
                const float* ap =
                    As + (warp_m * 64 + mf * 16 + grp) * PA + k8 * 8 + t4;
                a[mf][0] = cvt_tf32(ap[0]);
                a[mf][2] = cvt_tf32(ap[4]);
                a[mf][1] = cvt_tf32(ap[8 * PA]);
                a[mf][3] = cvt_tf32(ap[8 * PA + 4]);
            }
            #pragma unroll
            for (int nf = 0; nf < 4; nf++) {
                const float* bp =
                    Bs + (warp_n * 32 + nf * 8 + grp) * PA + k8 * 8 + t4;
                const uint32_t b0 = __float_as_uint(bp[0]);
                const uint32_t b1 = __float_as_uint(bp[4]);
                #pragma unroll
                for (int mf = 0; mf < 4; mf++)
                    mma_tf32(acc[mf][nf][0], acc[mf][nf][1],
                             acc[mf][nf][2], acc[mf][nf][3],
                             a[mf][0], a[mf][1], a[mf][2], a[mf][3], b0, b1);
            }
        }
        if (i + 1 < NCH) cp_async_wait_all();
        __syncthreads();
    }

    #pragma unroll
    for (int mf = 0; mf < 4; mf++) {
        const int row = bm + warp_m * 64 + mf * 16 + grp;
        #pragma unroll
        for (int nf = 0; nf < 4; nf++) {
            const int col = bn + warp_n * 32 + nf * 8 + t4 * 2;
            const float bx = __ldg(&bias[col]);
            const float by = __ldg(&bias[col + 1]);
            float2 lo, hi;
            lo.x = acc[mf][nf][0] + bx;
            lo.y = acc[mf][nf][1] + by;
            hi.x = acc[mf][nf][2] + bx;
            hi.y = acc[mf][nf][3] + by;
            *(float2*)&Cg[(size_t)row * N + col] = lo;
            *(float2*)&Cg[(size_t)(row + 8) * N + col] = hi;
        }
    }
}

// ---------------------------------------------------------------------------
// Tensor-core sliding-window attention.
// One CTA per (64-query tile, head). 256 threads = 8 warps.
// S(64x192) = Q @ K^T  via mma (warps 4m x 2n, warp tile 16x96)
// softmax with band mask (warp-private rows), P stored tf32 in smem
// ctx(64x64) = P @ V    via mma (warps 4m x 2n, warp tile 16x32)
// Pitches: PX=72 (Q/K/V; 72%32=8 -> both operand orientations conflict-free),
//          PSP=196 (S; 196%32=4 -> A-frag conflict-free).
// ---------------------------------------------------------------------------
static constexpr int PX = 72;
static constexpr int PSP = 196;
static constexpr int ATTN_SMEM =
    (QT * PX + 192 * PX + 192 * PX + QT * PSP) * 4;   // 179200 B

__global__ __launch_bounds__(256) void swa_tc_kernel()
{
    extern __shared__ float sma[];
    float* sQ = sma;                  // 64  x PX (tf32)
    float* sK = sQ + QT * PX;         // 192 x PX (tf32)
    float* sV = sK + 192 * PX;        // 192 x PX (tf32)
    float* sS = sV + 192 * PX;        // 64  x PSP (scores -> P)

    const int tid   = threadIdx.x;
    const int qbase = blockIdx.x * QT;
    const int h     = blockIdx.y;

    // ---- stage Q/K/V (float4 LDG, cvt to tf32 at store) ----
    for (int i = tid; i < QT * 16; i += 256) {        // 1024 float4
        const int r = i >> 4, d4 = i & 15;
        float4 v = *(const float4*)&g_q[(size_t)(qbase + r) * DMODEL
                                        + h * HD + d4 * 4];
        float* dst = sQ + r * PX + d4 * 4;
        dst[0] = cvt_tf32f(v.x); dst[1] = cvt_tf32f(v.y);
        dst[2] = cvt_tf32f(v.z); dst[3] = cvt_tf32f(v.w);
    }
    for (int i = tid; i < 192 * 16; i += 256) {       // 3072 float4 x2
        const int r = i >> 4, d4 = i & 15;
        const int pos = qbase - 64 + r;
        const bool ok = (pos >= 0) && (pos < SEQ);
        float4 kv = make_float4(0.f, 0.f, 0.f, 0.f);
        float4 vv = make_float4(0.f, 0.f, 0.f, 0.f);
        if (ok) {
            const size_t off = (size_t)pos * DMODEL + h * HD + d4 * 4;
            kv = *(const float4*)&g_k[off];
            vv = *(const float4*)&g_v[off];
        }
        float* dk = sK + r * PX + d4 * 4;
        float* dv = sV + r * PX + d4 * 4;
        dk[0] = cvt_tf32f(kv.x); dk[1] = cvt_tf32f(kv.y);
        dk[2] = cvt_tf32f(kv.z); dk[3] = cvt_tf32f(kv.w);
        dv[0] = cvt_tf32f(vv.x); dv[1] = cvt_tf32f(vv.y);
        dv[2] = cvt_tf32f(vv.z); dv[3] = cvt_tf32f(vv.w);
    }
    __syncthreads();

    const int wid  = tid >> 5;
    const int lane = tid & 31;
    const int grp  = lane >> 2;     // 0..7
    const int t4   = lane & 3;      // 0..3

    // ---- S = Q @ K^T (M=64, N=192, K=64) ----
    {
        const int m0 = (wid >> 1) * 16;      // warp_m 0..3
        const int n0 = (wid & 1) * 96;       // warp_n 0..1
        float sf[12][4];
        #pragma unroll
        for (int nf = 0; nf < 12; nf++)
            #pragma unroll
            for (int c = 0; c < 4; c++) sf[nf][c] = 0.f;

        #pragma unroll
        for (int k8 = 0; k8 < 8; k8++) {
            const float* ap = sQ + (m0 + grp) * PX + k8 * 8 + t4;
            const uint32_t a0 = __float_as_uint(ap[0]);
            const uint32_t a2 = __float_as_uint(ap[4]);
            const uint32_t a1 = __float_as_uint(ap[8 * PX]);
            const uint32_t a3 = __float_as_uint(ap[8 * PX + 4]);
            #pragma unroll
            for (int nf = 0; nf < 12; nf++) {
                const float* bp = sK + (n0 + nf * 8 + grp) * PX + k8 * 8 + t4;
                mma_tf32(sf[nf][0], sf[nf][1], sf[nf][2], sf[nf][3],
                         a0, a1, a2, a3,
                         __float_as_uint(bp[0]), __float_as_uint(bp[4]));
            }
        }
        // write scaled scores to sS
        #pragma unroll
        for (int nf = 0; nf < 12; nf++) {
            const int col = n0 + nf * 8 + t4 * 2;
            float2 lo, hi;
            lo.x = sf[nf][0] * 0.125f; lo.y = sf[nf][1] * 0.125f;
            hi.x = sf[nf][2] * 0.125f; hi.y = sf[nf][3] * 0.125f;
            *(float2*)&sS[(m0 + grp) * PSP + col] = lo;
            *(float2*)&sS[(m0 + grp + 8) * PSP + col] = hi;
        }
    }
    __syncthreads();

    // ---- softmax over band (warp owns rows wid*8..wid*8+7) ----
    for (int r8 = 0; r8 < 8; r8++) {
        const int qi = wid * 8 + r8;
        float v[6];
        bool ok[6];
        float m = -1e30f;
        #pragma unroll
        for (int c = 0; c < 6; c++) {
            const int j = lane + 32 * c;                  // 0..191
            const int pos = qbase - 64 + j;
            ok[c] = (j >= qi) && (j <= qi + 128) && (pos >= 0) && (pos < SEQ);
            v[c] = ok[c] ? sS[qi * PSP + j] : -1e30f;
            m = fmaxf(m, v[c]);
        }
        #pragma unroll
        for (int o = 16; o > 0; o >>= 1)
            m = fmaxf(m, __shfl_xor_sync(0xffffffffu, m, o));
        float sum = 0.f;
        #pragma unroll
        for (int c = 0; c < 6; c++) { v[c] = __expf(v[c] - m); sum += v[c]; }
        #pragma unroll
        for (int o = 16; o > 0; o >>= 1)
            sum += __shfl_xor_sync(0xffffffffu, sum, o);
        const float inv = __frcp_rn(sum);
        #pragma unroll
        for (int c = 0; c < 6; c++) {
            const int j = lane + 32 * c;
            sS[qi * PSP + j] = ok[c] ? cvt_tf32f(v[c] * inv) : 0.f;
        }
    }
    __syncthreads();

    // ---- ctx = P @ V (M=64, N=64, K=192) ----
    {
        const int m0 = (wid >> 1) * 16;
        const int n0 = (wid & 1) * 32;
        float cf[4][4];
        #pragma unroll
        for (int nf = 0; nf < 4; nf++)
            #pragma unroll
            for (int c = 0; c < 4; c++) cf[nf][c] = 0.f;

        #pragma unroll 4
        for (int k8 = 0; k8 < 24; k8++) {
            const float* ap = sS + (m0 + grp) * PSP + k8 * 8 + t4;
            const uint32_t a0 = __float_as_uint(ap[0]);
            const uint32_t a2 = __float_as_uint(ap[4]);
            const uint32_t a1 = __float_as_uint(ap[8 * PSP]);
            const uint32_t a3 = __float_as_uint(ap[8 * PSP + 4]);
            #pragma unroll
            for (int nf = 0; nf < 4; nf++) {
                const float* bp = sV + (k8 * 8 + t4) * PX + n0 + nf * 8 + grp;
                mma_tf32(cf[nf][0], cf[nf][1], cf[nf][2], cf[nf][3],
                         a0, a1, a2, a3,
                         __float_as_uint(bp[0]),
                         __float_as_uint(bp[4 * PX]));
            }
        }
        // write ctx fragments to gmem
        #pragma unroll
        for (int nf = 0; nf < 4; nf++) {
            const int col = h * HD + n0 + nf * 8 + t4 * 2;
            const size_t r1 = (size_t)(qbase + m0 + grp) * DMODEL + col;
            const size_t r2 = (size_t)(qbase + m0 + grp + 8) * DMODEL + col;
            float2 lo, hi;
            lo.x = cf[nf][0]; lo.y = cf[nf][1];
            hi.x = cf[nf][2]; hi.y = cf[nf][3];
            *(float2*)&g_ctx[r1] = lo;
            *(float2*)&g_ctx[r2] = hi;
        }
    }
}

// ---------------------------------------------------------------------------
extern "C" void kernel_launch(void* const* d_in, const int* in_sizes, int n_in,
                              void* d_out, int out_size)
{
    (void)in_sizes; (void)n_in; (void)out_size;
    const float* query = (const float*)d_in[0];
    const float* key   = (const float*)d_in[1];
    const float* value = (const float*)d_in[2];
    const float* Wq = (const float*)d_in[3];
    const float* bq = (const float*)d_in[4];
    const float* Wk = (const float*)d_in[5];
    const float* bk = (const float*)d_in[6];
    const float* Wv = (const float*)d_in[7];
    const float* bv = (const float*)d_in[8];
    const float* Wo = (const float*)d_in[9];
    const float* bo = (const float*)d_in[10];
    float* out = (float*)d_out;

    float *qp, *kp, *vp, *cp;
    cudaGetSymbolAddress((void**)&qp, g_q);
    cudaGetSymbolAddress((void**)&kp, g_k);
    cudaGetSymbolAddress((void**)&vp, g_v);
    cudaGetSymbolAddress((void**)&cp, g_ctx);

    cudaFuncSetAttribute(swa_tc_kernel,
                         cudaFuncAttributeMaxDynamicSharedMemorySize,
                         ATTN_SMEM);
    cudaFuncSetAttribute(tf32_gemm_kernel,
                         cudaFuncAttributeMaxDynamicSharedMemorySize,
                         GEMM_SMEM);

    // Fused QKV projection (tf32 mma.sync tensor cores)
    dim3 gproj(DMODEL / GN, SEQ / GM, 3);   // (6, 16, 3)
    tf32_gemm_kernel<<<gproj, 256, GEMM_SMEM>>>(
        query, Wq, bq, qp,
        key,   Wk, bk, kp,
        value, Wv, bv, vp,
        SEQ, DMODEL, DMODEL);

    // Tensor-core sliding-window attention
    swa_tc_kernel<<<dim3(SEQ / QT, NH), 256, ATTN_SMEM>>>();

    // Output projection -> d_out
    dim3 gout(DMODEL / GN, SEQ / GM, 1);    // (6, 16)
    tf32_gemm_kernel<<<gout, 256, GEMM_SMEM>>>(
        cp, Wo, bo, out,
        cp, Wo, bo, out,
        cp, Wo, bo, out,
        SEQ, DMODEL, DMODEL);
}